// round 10
// baseline (speedup 1.0000x reference)
#include <cuda_runtime.h>
#include <cuda_bf16.h>

// AggregationLoss on GB300 (sm_103a).
// pass1 (PXPT=2 for low reg pressure / high occupancy): per-batch segment sums
//        over 33 labels. ATOMS payload 4 ops / 12 B per px: (km,q0),(q1,q2)
//        bf16x2 + q3,rsum scalar bf16. 4-way bank-spread replicas, fp32 flush
//        -> global float atomics. Also writes Fp=pred*rmask (4x bf16) + packed
//        labels (u16) so pass2 reads 86.7 MB instead of 242.7 MB.
// pass2 (PXPT=4): per-pixel loss from compressed scratch + per-batch LUT.
// finalize: writes scalar, zeroes scratch for the next graph replay
//           (module-load zero-init covers the very first call).
//
// Shapes fixed: B=16, C=4, N = 736*736 = 541696.

#define BATCH 16
#define CHAN 4
#define NSEG 33
#define NQ 6          // g_tab: q0=ksum, q1..q4=psum[c], q5=rsum
#define NREP 4
#define THREADS 256
#define PXPT1 2       // pass1 pixels/thread (reg pressure)
#define PXPT2 4       // pass2 pixels/thread
#define NPX_CAP (16 * 736 * 736)   // 8,667,136

// ---- device scratch (allocation-free; zero at module load) ----
__device__ float  g_tab[BATCH][NQ][NSEG];
__device__ int    g_kmax;
__device__ double g_acc;
__device__ uint2          g_fp[NPX_CAP];   // Fp per px: 4x bf16
__device__ unsigned short g_lab[NPX_CAP];  // klab | (rlab<<8)

__device__ __forceinline__ unsigned int pack_bf2(float a, float b) {
    __nv_bfloat162 h = __floats2bfloat162_rn(a, b);
    return *(unsigned int*)&h;
}

__global__ void __launch_bounds__(THREADS) pass1_kernel(
    const float* __restrict__ pred,   // [B, C, N]
    const float* __restrict__ rmask,  // [B, N]
    const float* __restrict__ kmask,  // [B, N]
    const int*   __restrict__ klab,   // [B, N]
    const int*   __restrict__ rlab,   // [B, N]
    int N)
{
    __shared__ __nv_bfloat162 s_p01[NREP * NSEG];  // (km, q0)
    __shared__ __nv_bfloat162 s_p12[NREP * NSEG];  // (q1, q2)
    __shared__ __nv_bfloat16  s_q3[NREP * NSEG];   // q3
    __shared__ __nv_bfloat16  s_r[NREP * NSEG];    // rsum

    const int t = threadIdx.x;
    const int b = blockIdx.y;
    const int r = t & (NREP - 1);

    for (int i = t; i < NREP * NSEG; i += THREADS) {
        *(unsigned int*)&s_p01[i] = 0u;
        *(unsigned int*)&s_p12[i] = 0u;
        *(unsigned short*)&s_q3[i] = 0;
        *(unsigned short*)&s_r[i] = 0;
    }
    __syncthreads();

    const int n0 = (blockIdx.x * THREADS + t) * PXPT1;
    const size_t base = (size_t)b * N;
    int local_kmax = 0;

    if (n0 + PXPT1 <= N) {
        int2   kl2 = *(const int2*)(klab + base + n0);
        int2   rl2 = *(const int2*)(rlab + base + n0);
        float2 km2 = *(const float2*)(kmask + base + n0);
        float2 rm2 = *(const float2*)(rmask + base + n0);
        float2 pv[CHAN];
        const float* pb = pred + (size_t)b * CHAN * N + n0;
#pragma unroll
        for (int c = 0; c < CHAN; c++) pv[c] = *(const float2*)(pb + (size_t)c * N);

        int kls[2] = { kl2.x, kl2.y };
        int rls[2] = { rl2.x, rl2.y };
        float kms[2] = { km2.x, km2.y };
        float rms[2] = { rm2.x, rm2.y };
        float prs[CHAN][2];
#pragma unroll
        for (int c = 0; c < CHAN; c++) { prs[c][0] = pv[c].x; prs[c][1] = pv[c].y; }

        // Fp (pred*rmask) + packed labels: one uint4 + one uint store per 2 px
        const size_t gpx = base + n0;
        *(uint4*)&g_fp[gpx] = make_uint4(
            pack_bf2(prs[0][0] * rms[0], prs[1][0] * rms[0]),
            pack_bf2(prs[2][0] * rms[0], prs[3][0] * rms[0]),
            pack_bf2(prs[0][1] * rms[1], prs[1][1] * rms[1]),
            pack_bf2(prs[2][1] * rms[1], prs[3][1] * rms[1]));
        *(unsigned int*)&g_lab[gpx] =
            (unsigned int)(kls[0] | (rls[0] << 8))
            | ((unsigned int)(kls[1] | (rls[1] << 8)) << 16);

        // compressed smem atomics: 4 ops, 12 B per px
#pragma unroll
        for (int j = 0; j < PXPT1; j++) {
            const int kl = kls[j], rl = rls[j];
            const int idx = r * NSEG + kl;
            local_kmax = max(local_kmax, kl);
            atomicAdd(&s_p01[idx], __floats2bfloat162_rn(kms[j], prs[0][j]));
            atomicAdd(&s_p12[idx], __floats2bfloat162_rn(prs[1][j], prs[2][j]));
            atomicAdd(&s_q3[idx], __float2bfloat16_rn(prs[3][j]));
            atomicAdd(&s_r[r * NSEG + rl], __float2bfloat16_rn(kms[j]));
        }
    } else if (n0 < N) {
        const float* pb = pred + (size_t)b * CHAN * N;
        for (int j = 0; j < PXPT1; j++) {
            const int n = n0 + j;
            if (n >= N) break;
            const int kl = klab[base + n], rl = rlab[base + n];
            const float km = kmask[base + n];
            const float rm = rmask[base + n];
            const int idx = r * NSEG + kl;
            local_kmax = max(local_kmax, kl);
            float p[CHAN];
            for (int c = 0; c < CHAN; c++) p[c] = pb[(size_t)c * N + n];
            atomicAdd(&s_p01[idx], __floats2bfloat162_rn(km, p[0]));
            atomicAdd(&s_p12[idx], __floats2bfloat162_rn(p[1], p[2]));
            atomicAdd(&s_q3[idx], __float2bfloat16_rn(p[3]));
            atomicAdd(&s_r[r * NSEG + rl], __float2bfloat16_rn(km));
            g_fp[base + n].x = pack_bf2(p[0] * rm, p[1] * rm);
            g_fp[base + n].y = pack_bf2(p[2] * rm, p[3] * rm);
            g_lab[base + n] = (unsigned short)(kl | (rl << 8));
        }
    }
    __syncthreads();

    // flush: convert to fp32, sum replicas, one global atomic per (q,l)
    for (int i = t; i < NSEG; i += THREADS) {
        float vk = 0.f, v0 = 0.f, v1 = 0.f, v2 = 0.f, v3 = 0.f, vr = 0.f;
#pragma unroll
        for (int rr = 0; rr < NREP; rr++) {
            const int idx = rr * NSEG + i;
            float2 f01 = __bfloat1622float2(s_p01[idx]);
            float2 f12 = __bfloat1622float2(s_p12[idx]);
            vk += f01.x; v0 += f01.y;
            v1 += f12.x; v2 += f12.y;
            v3 += __bfloat162float(s_q3[idx]);
            vr += __bfloat162float(s_r[idx]);
        }
        if (vk != 0.f) atomicAdd(&g_tab[b][0][i], vk);
        if (v0 != 0.f) atomicAdd(&g_tab[b][1][i], v0);
        if (v1 != 0.f) atomicAdd(&g_tab[b][2][i], v1);
        if (v2 != 0.f) atomicAdd(&g_tab[b][3][i], v2);
        if (v3 != 0.f) atomicAdd(&g_tab[b][4][i], v3);
        if (vr != 0.f) atomicAdd(&g_tab[b][5][i], vr);
    }

    if (b == BATCH - 1) {
#pragma unroll
        for (int o = 16; o; o >>= 1)
            local_kmax = max(local_kmax, __shfl_xor_sync(0xffffffffu, local_kmax, o));
        if ((t & 31) == 0) atomicMax(&g_kmax, local_kmax);
    }
}

__global__ void __launch_bounds__(THREADS) pass2_kernel(int N)
{
    __shared__ float s_gc[CHAN][NSEG];
    __shared__ float s_rinv[NSEG];
    __shared__ float s_part[THREADS / 32];

    const int t = threadIdx.x;
    const int b = blockIdx.y;

    if (t < NSEG) {
        const float invk = (t == 0) ? 0.f : 1.f / (g_tab[b][0][t] + 1.f);
#pragma unroll
        for (int c = 0; c < CHAN; c++) s_gc[c][t] = g_tab[b][1 + c][t] * invk;
        s_rinv[t] = (t == 0) ? 1.f : 1.f / (g_tab[b][5][t] + 1.f);
    }
    __syncthreads();

    float acc = 0.f;
    const int n0 = (blockIdx.x * THREADS + t) * PXPT2;
    const size_t base = (size_t)b * N;
    const size_t gpx = base + n0;

    if (n0 + PXPT2 <= N) {
        uint4 f01 = *(const uint4*)&g_fp[gpx];
        uint4 f23 = *(const uint4*)&g_fp[gpx + 2];
        uint2 lab = *(const uint2*)&g_lab[gpx];
        unsigned int fps[4][2] = {
            { f01.x, f01.y }, { f01.z, f01.w },
            { f23.x, f23.y }, { f23.z, f23.w } };
        unsigned short ws[4] = {
            (unsigned short)(lab.x & 0xffff), (unsigned short)(lab.x >> 16),
            (unsigned short)(lab.y & 0xffff), (unsigned short)(lab.y >> 16) };
#pragma unroll
        for (int j = 0; j < 4; j++) {
            const int kl = ws[j] & 0xff;
            const int rl = ws[j] >> 8;
            float2 f01v = __bfloat1622float2(*(__nv_bfloat162*)&fps[j][0]);
            float2 f23v = __bfloat1622float2(*(__nv_bfloat162*)&fps[j][1]);
            float d0 = f01v.x - s_gc[0][kl];
            float d1 = f01v.y - s_gc[1][kl];
            float d2 = f23v.x - s_gc[2][kl];
            float d3 = f23v.y - s_gc[3][kl];
            float n2 = fmaf(d0, d0, fmaf(d1, d1, fmaf(d2, d2, d3 * d3)));
            float nr = sqrtf(n2);
            float dd = fmaxf(nr - 0.5f, 0.f);
            acc += __logf(fmaf(dd, dd, 1.f)) * s_rinv[rl];
        }
    } else if (n0 < N) {
        for (int j = 0; j < PXPT2; j++) {
            const int n = n0 + j;
            if (n >= N) break;
            const unsigned short w = g_lab[base + n];
            const int kl = w & 0xff;
            const int rl = w >> 8;
            uint2 f = g_fp[base + n];
            float2 f01v = __bfloat1622float2(*(__nv_bfloat162*)&f.x);
            float2 f23v = __bfloat1622float2(*(__nv_bfloat162*)&f.y);
            float d0 = f01v.x - s_gc[0][kl];
            float d1 = f01v.y - s_gc[1][kl];
            float d2 = f23v.x - s_gc[2][kl];
            float d3 = f23v.y - s_gc[3][kl];
            float n2 = fmaf(d0, d0, fmaf(d1, d1, fmaf(d2, d2, d3 * d3)));
            float nr = sqrtf(n2);
            float dd = fmaxf(nr - 0.5f, 0.f);
            acc += __logf(fmaf(dd, dd, 1.f)) * s_rinv[rl];
        }
    }

#pragma unroll
    for (int o = 16; o; o >>= 1) acc += __shfl_xor_sync(0xffffffffu, acc, o);
    if ((t & 31) == 0) s_part[t >> 5] = acc;
    __syncthreads();
    if (t == 0) {
        float s = 0.f;
#pragma unroll
        for (int i = 0; i < THREADS / 32; i++) s += s_part[i];
        atomicAdd(&g_acc, (double)s);
    }
}

__global__ void finalize_kernel(float* __restrict__ out) {
    const int t = threadIdx.x;
    if (t == 0) out[0] = (float)(g_acc / (double)g_kmax);
    __syncthreads();
    float* tp = &g_tab[0][0][0];
    for (int i = t; i < BATCH * NQ * NSEG; i += blockDim.x) tp[i] = 0.f;
    if (t == 0) { g_kmax = 0; g_acc = 0.0; }
}

extern "C" void kernel_launch(void* const* d_in, const int* in_sizes, int n_in,
                              void* d_out, int out_size) {
    const float* pred  = (const float*)d_in[0];
    const float* rmask = (const float*)d_in[1];
    const float* kmask = (const float*)d_in[2];
    const int*   rlab  = (const int*)d_in[3];
    const int*   klab  = (const int*)d_in[4];

    const int N = in_sizes[1] / BATCH;
    const int blocks1 = (N + THREADS * PXPT1 - 1) / (THREADS * PXPT1);
    const int blocks2 = (N + THREADS * PXPT2 - 1) / (THREADS * PXPT2);
    dim3 grid1(blocks1, BATCH);
    dim3 grid2(blocks2, BATCH);

    pass1_kernel<<<grid1, THREADS>>>(pred, rmask, kmask, klab, rlab, N);
    pass2_kernel<<<grid2, THREADS>>>(N);
    finalize_kernel<<<1, 256>>>((float*)d_out);
}

// round 11
// speedup vs baseline: 1.4144x; 1.4144x over previous
#include <cuda_runtime.h>
#include <cuda_bf16.h>

// AggregationLoss on GB300 (sm_103a).
// pass1 (PXPT=4, __launch_bounds__(256,6) to cap regs ~42 and keep occupancy
//        ~70%): per-batch segment sums over 33 labels. ATOMS payload 4 ops /
//        12 B per px: (km,q0),(q1,q2) bf16x2 + q3,rsum scalar bf16. 4-way
//        bank-spread replicas, fp32 flush -> global float atomics. Also writes
//        Fp=pred*rmask (4x bf16) + packed labels (u16) so pass2 reads 86.7 MB
//        instead of 242.7 MB.
// pass2 (PXPT=4): per-pixel loss from compressed scratch + per-batch LUT.
// finalize: writes scalar, zeroes scratch for the next graph replay
//           (module-load zero-init covers the very first call).
//
// Shapes fixed: B=16, C=4, N = 736*736 = 541696.

#define BATCH 16
#define CHAN 4
#define NSEG 33
#define NQ 6          // g_tab: q0=ksum, q1..q4=psum[c], q5=rsum
#define NREP 4
#define THREADS 256
#define PXPT 4
#define NPX_CAP (16 * 736 * 736)   // 8,667,136

// ---- device scratch (allocation-free; zero at module load) ----
__device__ float  g_tab[BATCH][NQ][NSEG];
__device__ int    g_kmax;
__device__ double g_acc;
__device__ uint2          g_fp[NPX_CAP];   // Fp per px: 4x bf16
__device__ unsigned short g_lab[NPX_CAP];  // klab | (rlab<<8)

__device__ __forceinline__ unsigned int pack_bf2(float a, float b) {
    __nv_bfloat162 h = __floats2bfloat162_rn(a, b);
    return *(unsigned int*)&h;
}

__global__ void __launch_bounds__(THREADS, 6) pass1_kernel(
    const float* __restrict__ pred,   // [B, C, N]
    const float* __restrict__ rmask,  // [B, N]
    const float* __restrict__ kmask,  // [B, N]
    const int*   __restrict__ klab,   // [B, N]
    const int*   __restrict__ rlab,   // [B, N]
    int N)
{
    __shared__ __nv_bfloat162 s_p01[NREP * NSEG];  // (km, q0)
    __shared__ __nv_bfloat162 s_p12[NREP * NSEG];  // (q1, q2)
    __shared__ __nv_bfloat16  s_q3[NREP * NSEG];   // q3
    __shared__ __nv_bfloat16  s_r[NREP * NSEG];    // rsum

    const int t = threadIdx.x;
    const int b = blockIdx.y;
    const int r = t & (NREP - 1);

    for (int i = t; i < NREP * NSEG; i += THREADS) {
        *(unsigned int*)&s_p01[i] = 0u;
        *(unsigned int*)&s_p12[i] = 0u;
        *(unsigned short*)&s_q3[i] = 0;
        *(unsigned short*)&s_r[i] = 0;
    }
    __syncthreads();

    const int n0 = (blockIdx.x * THREADS + t) * PXPT;
    const size_t base = (size_t)b * N;
    int local_kmax = 0;

    if (n0 + PXPT <= N) {
        int4   kl4 = *(const int4*)(klab + base + n0);
        int4   rl4 = *(const int4*)(rlab + base + n0);
        float4 km4 = *(const float4*)(kmask + base + n0);
        float4 rm4 = *(const float4*)(rmask + base + n0);
        float4 pv[CHAN];
        const float* pb = pred + (size_t)b * CHAN * N + n0;
#pragma unroll
        for (int c = 0; c < CHAN; c++) pv[c] = *(const float4*)(pb + (size_t)c * N);

        int kls[4] = { kl4.x, kl4.y, kl4.z, kl4.w };
        int rls[4] = { rl4.x, rl4.y, rl4.z, rl4.w };
        float kms[4] = { km4.x, km4.y, km4.z, km4.w };
        float rms[4] = { rm4.x, rm4.y, rm4.z, rm4.w };
        float prs[CHAN][4];
#pragma unroll
        for (int c = 0; c < CHAN; c++) {
            prs[c][0] = pv[c].x; prs[c][1] = pv[c].y;
            prs[c][2] = pv[c].z; prs[c][3] = pv[c].w;
        }

        // Fp (pred*rmask) as bf16x4 per px + packed labels (consumes rms)
        const size_t gpx = base + n0;
        *(uint4*)&g_fp[gpx] = make_uint4(
            pack_bf2(prs[0][0] * rms[0], prs[1][0] * rms[0]),
            pack_bf2(prs[2][0] * rms[0], prs[3][0] * rms[0]),
            pack_bf2(prs[0][1] * rms[1], prs[1][1] * rms[1]),
            pack_bf2(prs[2][1] * rms[1], prs[3][1] * rms[1]));
        *(uint4*)&g_fp[gpx + 2] = make_uint4(
            pack_bf2(prs[0][2] * rms[2], prs[1][2] * rms[2]),
            pack_bf2(prs[2][2] * rms[2], prs[3][2] * rms[2]),
            pack_bf2(prs[0][3] * rms[3], prs[1][3] * rms[3]),
            pack_bf2(prs[2][3] * rms[3], prs[3][3] * rms[3]));
        *(uint2*)&g_lab[gpx] = make_uint2(
            (unsigned int)(kls[0] | (rls[0] << 8))
                | ((unsigned int)(kls[1] | (rls[1] << 8)) << 16),
            (unsigned int)(kls[2] | (rls[2] << 8))
                | ((unsigned int)(kls[3] | (rls[3] << 8)) << 16));

        // compressed smem atomics: 4 ops, 12 B per px
#pragma unroll
        for (int j = 0; j < 4; j++) {
            const int kl = kls[j], rl = rls[j];
            const int idx = r * NSEG + kl;
            local_kmax = max(local_kmax, kl);
            atomicAdd(&s_p01[idx], __floats2bfloat162_rn(kms[j], prs[0][j]));
            atomicAdd(&s_p12[idx], __floats2bfloat162_rn(prs[1][j], prs[2][j]));
            atomicAdd(&s_q3[idx], __float2bfloat16_rn(prs[3][j]));
            atomicAdd(&s_r[r * NSEG + rl], __float2bfloat16_rn(kms[j]));
        }
    } else if (n0 < N) {
        const float* pb = pred + (size_t)b * CHAN * N;
        for (int j = 0; j < PXPT; j++) {
            const int n = n0 + j;
            if (n >= N) break;
            const int kl = klab[base + n], rl = rlab[base + n];
            const float km = kmask[base + n];
            const float rm = rmask[base + n];
            const int idx = r * NSEG + kl;
            local_kmax = max(local_kmax, kl);
            float p[CHAN];
            for (int c = 0; c < CHAN; c++) p[c] = pb[(size_t)c * N + n];
            atomicAdd(&s_p01[idx], __floats2bfloat162_rn(km, p[0]));
            atomicAdd(&s_p12[idx], __floats2bfloat162_rn(p[1], p[2]));
            atomicAdd(&s_q3[idx], __float2bfloat16_rn(p[3]));
            atomicAdd(&s_r[r * NSEG + rl], __float2bfloat16_rn(km));
            g_fp[base + n].x = pack_bf2(p[0] * rm, p[1] * rm);
            g_fp[base + n].y = pack_bf2(p[2] * rm, p[3] * rm);
            g_lab[base + n] = (unsigned short)(kl | (rl << 8));
        }
    }
    __syncthreads();

    // flush: convert to fp32, sum replicas, one global atomic per (q,l)
    for (int i = t; i < NSEG; i += THREADS) {
        float vk = 0.f, v0 = 0.f, v1 = 0.f, v2 = 0.f, v3 = 0.f, vr = 0.f;
#pragma unroll
        for (int rr = 0; rr < NREP; rr++) {
            const int idx = rr * NSEG + i;
            float2 f01 = __bfloat1622float2(s_p01[idx]);
            float2 f12 = __bfloat1622float2(s_p12[idx]);
            vk += f01.x; v0 += f01.y;
            v1 += f12.x; v2 += f12.y;
            v3 += __bfloat162float(s_q3[idx]);
            vr += __bfloat162float(s_r[idx]);
        }
        if (vk != 0.f) atomicAdd(&g_tab[b][0][i], vk);
        if (v0 != 0.f) atomicAdd(&g_tab[b][1][i], v0);
        if (v1 != 0.f) atomicAdd(&g_tab[b][2][i], v1);
        if (v2 != 0.f) atomicAdd(&g_tab[b][3][i], v2);
        if (v3 != 0.f) atomicAdd(&g_tab[b][4][i], v3);
        if (vr != 0.f) atomicAdd(&g_tab[b][5][i], vr);
    }

    if (b == BATCH - 1) {
#pragma unroll
        for (int o = 16; o; o >>= 1)
            local_kmax = max(local_kmax, __shfl_xor_sync(0xffffffffu, local_kmax, o));
        if ((t & 31) == 0) atomicMax(&g_kmax, local_kmax);
    }
}

__global__ void __launch_bounds__(THREADS) pass2_kernel(int N)
{
    __shared__ float s_gc[CHAN][NSEG];
    __shared__ float s_rinv[NSEG];
    __shared__ float s_part[THREADS / 32];

    const int t = threadIdx.x;
    const int b = blockIdx.y;

    if (t < NSEG) {
        const float invk = (t == 0) ? 0.f : 1.f / (g_tab[b][0][t] + 1.f);
#pragma unroll
        for (int c = 0; c < CHAN; c++) s_gc[c][t] = g_tab[b][1 + c][t] * invk;
        s_rinv[t] = (t == 0) ? 1.f : 1.f / (g_tab[b][5][t] + 1.f);
    }
    __syncthreads();

    float acc = 0.f;
    const int n0 = (blockIdx.x * THREADS + t) * PXPT;
    const size_t base = (size_t)b * N;
    const size_t gpx = base + n0;

    if (n0 + PXPT <= N) {
        uint4 f01 = *(const uint4*)&g_fp[gpx];
        uint4 f23 = *(const uint4*)&g_fp[gpx + 2];
        uint2 lab = *(const uint2*)&g_lab[gpx];
        unsigned int fps[4][2] = {
            { f01.x, f01.y }, { f01.z, f01.w },
            { f23.x, f23.y }, { f23.z, f23.w } };
        unsigned short ws[4] = {
            (unsigned short)(lab.x & 0xffff), (unsigned short)(lab.x >> 16),
            (unsigned short)(lab.y & 0xffff), (unsigned short)(lab.y >> 16) };
#pragma unroll
        for (int j = 0; j < 4; j++) {
            const int kl = ws[j] & 0xff;
            const int rl = ws[j] >> 8;
            float2 f01v = __bfloat1622float2(*(__nv_bfloat162*)&fps[j][0]);
            float2 f23v = __bfloat1622float2(*(__nv_bfloat162*)&fps[j][1]);
            float d0 = f01v.x - s_gc[0][kl];
            float d1 = f01v.y - s_gc[1][kl];
            float d2 = f23v.x - s_gc[2][kl];
            float d3 = f23v.y - s_gc[3][kl];
            float n2 = fmaf(d0, d0, fmaf(d1, d1, fmaf(d2, d2, d3 * d3)));
            float nr = sqrtf(n2);
            float dd = fmaxf(nr - 0.5f, 0.f);
            acc += __logf(fmaf(dd, dd, 1.f)) * s_rinv[rl];
        }
    } else if (n0 < N) {
        for (int j = 0; j < PXPT; j++) {
            const int n = n0 + j;
            if (n >= N) break;
            const unsigned short w = g_lab[base + n];
            const int kl = w & 0xff;
            const int rl = w >> 8;
            uint2 f = g_fp[base + n];
            float2 f01v = __bfloat1622float2(*(__nv_bfloat162*)&f.x);
            float2 f23v = __bfloat1622float2(*(__nv_bfloat162*)&f.y);
            float d0 = f01v.x - s_gc[0][kl];
            float d1 = f01v.y - s_gc[1][kl];
            float d2 = f23v.x - s_gc[2][kl];
            float d3 = f23v.y - s_gc[3][kl];
            float n2 = fmaf(d0, d0, fmaf(d1, d1, fmaf(d2, d2, d3 * d3)));
            float nr = sqrtf(n2);
            float dd = fmaxf(nr - 0.5f, 0.f);
            acc += __logf(fmaf(dd, dd, 1.f)) * s_rinv[rl];
        }
    }

#pragma unroll
    for (int o = 16; o; o >>= 1) acc += __shfl_xor_sync(0xffffffffu, acc, o);
    if ((t & 31) == 0) s_part[t >> 5] = acc;
    __syncthreads();
    if (t == 0) {
        float s = 0.f;
#pragma unroll
        for (int i = 0; i < THREADS / 32; i++) s += s_part[i];
        atomicAdd(&g_acc, (double)s);
    }
}

__global__ void finalize_kernel(float* __restrict__ out) {
    const int t = threadIdx.x;
    if (t == 0) out[0] = (float)(g_acc / (double)g_kmax);
    __syncthreads();
    float* tp = &g_tab[0][0][0];
    for (int i = t; i < BATCH * NQ * NSEG; i += blockDim.x) tp[i] = 0.f;
    if (t == 0) { g_kmax = 0; g_acc = 0.0; }
}

extern "C" void kernel_launch(void* const* d_in, const int* in_sizes, int n_in,
                              void* d_out, int out_size) {
    const float* pred  = (const float*)d_in[0];
    const float* rmask = (const float*)d_in[1];
    const float* kmask = (const float*)d_in[2];
    const int*   rlab  = (const int*)d_in[3];
    const int*   klab  = (const int*)d_in[4];

    const int N = in_sizes[1] / BATCH;
    const int blocks = (N + THREADS * PXPT - 1) / (THREADS * PXPT);
    dim3 grid(blocks, BATCH);

    pass1_kernel<<<grid, THREADS>>>(pred, rmask, kmask, klab, rlab, N);
    pass2_kernel<<<grid, THREADS>>>(N);
    finalize_kernel<<<1, 256>>>((float*)d_out);
}

// round 12
// speedup vs baseline: 1.6125x; 1.1401x over previous
#include <cuda_runtime.h>
#include <cuda_bf16.h>

// AggregationLoss on GB300 (sm_103a).
// pass1: per-batch segment sums over 33 labels with 3 smem ATOMS / 10 B per px:
//        psum pairs (q0,q1),(q2,q3) as bf16x2 binned by klab, plus a joint
//        bf16 table T[kl][rl] += kmask whose row sums give ksum and column
//        sums give rsum (one atomic replaces two). Also stores packed labels
//        (u16 = kl | rl<<8, one STG.64 per 4 px) so pass2 skips klab/rlab.
//        LDG/STG/ATOMS all share the LSU (measured R8 vs R11), so total LSU
//        ops drop 23 -> 21 per 4 px vs R8.
// pass2: DRAM-bound loss pass reading pred + rmask (fp32) + packed labels
//        (191 MB instead of 243 MB), Fp computed inline, per-batch LUT in smem.
// finalize: writes scalar, zeroes g_tab for the next graph replay
//        (g_lab is fully overwritten each call; module-load zero-init covers
//        the very first call's g_tab).
//
// Shapes fixed: B=16, C=4, N = 736*736 = 541696.

#define BATCH 16
#define CHAN 4
#define NSEG 33
#define NQ 6          // g_tab: q0=ksum, q1..q4=psum[c], q5=rsum
#define NREP 4        // replicas for psum pair tables
#define JREP 2        // replicas for joint (kl,rl) table
#define THREADS 256
#define PXPT 4
#define NPX_CAP (16 * 736 * 736)   // 8,667,136

// ---- device scratch (allocation-free; zero at module load) ----
__device__ float  g_tab[BATCH][NQ][NSEG];
__device__ int    g_kmax;
__device__ double g_acc;
__device__ unsigned short g_lab[NPX_CAP];  // klab | (rlab<<8)

__global__ void __launch_bounds__(THREADS) pass1_kernel(
    const float* __restrict__ pred,   // [B, C, N]
    const float* __restrict__ kmask,  // [B, N]
    const int*   __restrict__ klab,   // [B, N]
    const int*   __restrict__ rlab,   // [B, N]
    int N)
{
    __shared__ __nv_bfloat162 s_pA[NREP * NSEG];        // (q0, q1)
    __shared__ __nv_bfloat162 s_pB[NREP * NSEG];        // (q2, q3)
    __shared__ __nv_bfloat16  s_j[JREP * NSEG * NSEG];  // km joint table

    const int t = threadIdx.x;
    const int b = blockIdx.y;
    const int r = t & (NREP - 1);
    const int jr = (t & 1) * (NSEG * NSEG);

    for (int i = t; i < NREP * NSEG; i += THREADS) {
        *(unsigned int*)&s_pA[i] = 0u;
        *(unsigned int*)&s_pB[i] = 0u;
    }
    for (int i = t; i < JREP * NSEG * NSEG; i += THREADS)
        *(unsigned short*)&s_j[i] = 0;
    __syncthreads();

    const int n0 = (blockIdx.x * THREADS + t) * PXPT;
    const size_t base = (size_t)b * N;
    int local_kmax = 0;

    if (n0 + PXPT <= N) {
        int4   kl4 = *(const int4*)(klab + base + n0);
        int4   rl4 = *(const int4*)(rlab + base + n0);
        float4 km4 = *(const float4*)(kmask + base + n0);
        float4 pv[CHAN];
        const float* pb = pred + (size_t)b * CHAN * N + n0;
#pragma unroll
        for (int c = 0; c < CHAN; c++) pv[c] = *(const float4*)(pb + (size_t)c * N);

        int kls[4] = { kl4.x, kl4.y, kl4.z, kl4.w };
        int rls[4] = { rl4.x, rl4.y, rl4.z, rl4.w };
        float kms[4] = { km4.x, km4.y, km4.z, km4.w };
        float prs[CHAN][4];
#pragma unroll
        for (int c = 0; c < CHAN; c++) {
            prs[c][0] = pv[c].x; prs[c][1] = pv[c].y;
            prs[c][2] = pv[c].z; prs[c][3] = pv[c].w;
        }

        // packed labels: one STG.64 per 4 px
        *(uint2*)&g_lab[base + n0] = make_uint2(
            (unsigned int)(kls[0] | (rls[0] << 8))
                | ((unsigned int)(kls[1] | (rls[1] << 8)) << 16),
            (unsigned int)(kls[2] | (rls[2] << 8))
                | ((unsigned int)(kls[3] | (rls[3] << 8)) << 16));

        // 3 smem atomics / 10 B per px
#pragma unroll
        for (int j = 0; j < 4; j++) {
            const int kl = kls[j], rl = rls[j];
            const int idx = r * NSEG + kl;
            local_kmax = max(local_kmax, kl);
            atomicAdd(&s_pA[idx], __floats2bfloat162_rn(prs[0][j], prs[1][j]));
            atomicAdd(&s_pB[idx], __floats2bfloat162_rn(prs[2][j], prs[3][j]));
            atomicAdd(&s_j[jr + kl * NSEG + rl], __float2bfloat16_rn(kms[j]));
        }
    } else if (n0 < N) {
        const float* pb = pred + (size_t)b * CHAN * N;
        for (int j = 0; j < PXPT; j++) {
            const int n = n0 + j;
            if (n >= N) break;
            const int kl = klab[base + n], rl = rlab[base + n];
            const float km = kmask[base + n];
            const int idx = r * NSEG + kl;
            local_kmax = max(local_kmax, kl);
            atomicAdd(&s_pA[idx], __floats2bfloat162_rn(pb[0 * (size_t)N + n],
                                                        pb[1 * (size_t)N + n]));
            atomicAdd(&s_pB[idx], __floats2bfloat162_rn(pb[2 * (size_t)N + n],
                                                        pb[3 * (size_t)N + n]));
            atomicAdd(&s_j[jr + kl * NSEG + rl], __float2bfloat16_rn(km));
            g_lab[base + n] = (unsigned short)(kl | (rl << 8));
        }
    }
    __syncthreads();

    // flush: psum from replicas; ksum = row sums, rsum = col sums of joint tbl
    for (int i = t; i < NSEG; i += THREADS) {
        float v0 = 0.f, v1 = 0.f, v2 = 0.f, v3 = 0.f;
#pragma unroll
        for (int rr = 0; rr < NREP; rr++) {
            float2 fA = __bfloat1622float2(s_pA[rr * NSEG + i]);
            float2 fB = __bfloat1622float2(s_pB[rr * NSEG + i]);
            v0 += fA.x; v1 += fA.y; v2 += fB.x; v3 += fB.y;
        }
        float ks = 0.f, rs = 0.f;
        for (int o = 0; o < NSEG; o++) {
#pragma unroll
            for (int rep = 0; rep < JREP; rep++) {
                ks += __bfloat162float(s_j[rep * NSEG * NSEG + i * NSEG + o]);
                rs += __bfloat162float(s_j[rep * NSEG * NSEG + o * NSEG + i]);
            }
        }
        if (ks != 0.f) atomicAdd(&g_tab[b][0][i], ks);
        if (v0 != 0.f) atomicAdd(&g_tab[b][1][i], v0);
        if (v1 != 0.f) atomicAdd(&g_tab[b][2][i], v1);
        if (v2 != 0.f) atomicAdd(&g_tab[b][3][i], v2);
        if (v3 != 0.f) atomicAdd(&g_tab[b][4][i], v3);
        if (rs != 0.f) atomicAdd(&g_tab[b][5][i], rs);
    }

    if (b == BATCH - 1) {
#pragma unroll
        for (int o = 16; o; o >>= 1)
            local_kmax = max(local_kmax, __shfl_xor_sync(0xffffffffu, local_kmax, o));
        if ((t & 31) == 0) atomicMax(&g_kmax, local_kmax);
    }
}

__global__ void __launch_bounds__(THREADS) pass2_kernel(
    const float* __restrict__ pred,   // [B, C, N]
    const float* __restrict__ rmask,  // [B, N]
    int N)
{
    __shared__ float s_gc[CHAN][NSEG];
    __shared__ float s_rinv[NSEG];
    __shared__ float s_part[THREADS / 32];

    const int t = threadIdx.x;
    const int b = blockIdx.y;

    if (t < NSEG) {
        const float invk = (t == 0) ? 0.f : 1.f / (g_tab[b][0][t] + 1.f);
#pragma unroll
        for (int c = 0; c < CHAN; c++) s_gc[c][t] = g_tab[b][1 + c][t] * invk;
        s_rinv[t] = (t == 0) ? 1.f : 1.f / (g_tab[b][5][t] + 1.f);
    }
    __syncthreads();

    float acc = 0.f;
    const int n0 = (blockIdx.x * THREADS + t) * PXPT;
    const size_t base = (size_t)b * N;

    if (n0 + PXPT <= N) {
        uint2  lab = *(const uint2*)&g_lab[base + n0];
        float4 rm4 = *(const float4*)(rmask + base + n0);
        float4 pv[CHAN];
        const float* pb = pred + (size_t)b * CHAN * N + n0;
#pragma unroll
        for (int c = 0; c < CHAN; c++) pv[c] = *(const float4*)(pb + (size_t)c * N);

        unsigned short ws[4] = {
            (unsigned short)(lab.x & 0xffff), (unsigned short)(lab.x >> 16),
            (unsigned short)(lab.y & 0xffff), (unsigned short)(lab.y >> 16) };
        float rms[4] = { rm4.x, rm4.y, rm4.z, rm4.w };
        float prs[CHAN][4];
#pragma unroll
        for (int c = 0; c < CHAN; c++) {
            prs[c][0] = pv[c].x; prs[c][1] = pv[c].y;
            prs[c][2] = pv[c].z; prs[c][3] = pv[c].w;
        }
#pragma unroll
        for (int j = 0; j < 4; j++) {
            const int kl = ws[j] & 0xff;
            const int rl = ws[j] >> 8;
            const float rm = rms[j];
            float n2 = 0.f;
#pragma unroll
            for (int c = 0; c < CHAN; c++) {
                float d = fmaf(prs[c][j], rm, -s_gc[c][kl]);
                n2 = fmaf(d, d, n2);
            }
            float nr = sqrtf(n2);
            float dd = fmaxf(nr - 0.5f, 0.f);
            acc += __logf(fmaf(dd, dd, 1.f)) * s_rinv[rl];
        }
    } else if (n0 < N) {
        const float* pb = pred + (size_t)b * CHAN * N;
        for (int j = 0; j < PXPT; j++) {
            const int n = n0 + j;
            if (n >= N) break;
            const unsigned short w = g_lab[base + n];
            const int kl = w & 0xff;
            const int rl = w >> 8;
            const float rm = rmask[base + n];
            float n2 = 0.f;
            for (int c = 0; c < CHAN; c++) {
                float d = fmaf(pb[(size_t)c * N + n], rm, -s_gc[c][kl]);
                n2 = fmaf(d, d, n2);
            }
            float nr = sqrtf(n2);
            float dd = fmaxf(nr - 0.5f, 0.f);
            acc += __logf(fmaf(dd, dd, 1.f)) * s_rinv[rl];
        }
    }

#pragma unroll
    for (int o = 16; o; o >>= 1) acc += __shfl_xor_sync(0xffffffffu, acc, o);
    if ((t & 31) == 0) s_part[t >> 5] = acc;
    __syncthreads();
    if (t == 0) {
        float s = 0.f;
#pragma unroll
        for (int i = 0; i < THREADS / 32; i++) s += s_part[i];
        atomicAdd(&g_acc, (double)s);
    }
}

__global__ void finalize_kernel(float* __restrict__ out) {
    const int t = threadIdx.x;
    if (t == 0) out[0] = (float)(g_acc / (double)g_kmax);
    __syncthreads();
    float* tp = &g_tab[0][0][0];
    for (int i = t; i < BATCH * NQ * NSEG; i += blockDim.x) tp[i] = 0.f;
    if (t == 0) { g_kmax = 0; g_acc = 0.0; }
}

extern "C" void kernel_launch(void* const* d_in, const int* in_sizes, int n_in,
                              void* d_out, int out_size) {
    const float* pred  = (const float*)d_in[0];
    const float* rmask = (const float*)d_in[1];
    const float* kmask = (const float*)d_in[2];
    const int*   rlab  = (const int*)d_in[3];
    const int*   klab  = (const int*)d_in[4];

    const int N = in_sizes[1] / BATCH;
    const int blocks = (N + THREADS * PXPT - 1) / (THREADS * PXPT);
    dim3 grid(blocks, BATCH);

    pass1_kernel<<<grid, THREADS>>>(pred, kmask, klab, rlab, N);
    pass2_kernel<<<grid, THREADS>>>(pred, rmask, N);
    finalize_kernel<<<1, 256>>>((float*)d_out);
}